// round 5
// baseline (speedup 1.0000x reference)
#include <cuda_runtime.h>
#include <cstdint>

#define B_ 4
#define L_ 512
#define D_ 256
#define U_ 64

// scratch for projections (allowed: __device__ globals, no allocation)
__device__ float g_q [B_*L_*U_];     // [b][row][u]
__device__ float g_kT[B_*U_*L_];     // [b][u][row]  (transposed for coalesced score loads)

__device__ __forceinline__ float tanh_ap(float x){ float y; asm("tanh.approx.f32 %0, %1;" : "=f"(y) : "f"(x)); return y; }
__device__ __forceinline__ float ex2_ap(float x){ float y; asm("ex2.approx.f32 %0, %1;" : "=f"(y) : "f"(x)); return y; }
__device__ __forceinline__ unsigned long long dup2(float x){
    unsigned long long r; asm("mov.b64 %0, {%1, %1};" : "=l"(r) : "f"(x)); return r;
}
__device__ __forceinline__ unsigned long long pack2f(float a, float b){
    unsigned long long r; asm("mov.b64 %0, {%1, %2};" : "=l"(r) : "f"(a), "f"(b)); return r;
}
__device__ __forceinline__ void fma2(unsigned long long &a, unsigned long long x, unsigned long long y){
    asm("fma.rn.f32x2 %0, %1, %2, %0;" : "+l"(a) : "l"(x), "l"(y));
}
__device__ __forceinline__ float2 unpack2(unsigned long long v){
    float lo, hi; asm("mov.b64 {%0, %1}, %2;" : "=f"(lo), "=f"(hi) : "l"(v)); return make_float2(lo, hi);
}

// ---------------------------------------------------------------------------
// Phase 1: q = X@Wt ; k = X@Wx + bh.  256 blocks x 128 threads.
// q stored row-major; k stored TRANSPOSED per batch: g_kT[b][u][row].
// ---------------------------------------------------------------------------
__global__ void __launch_bounds__(128) proj_kernel(
    const float* __restrict__ X, const float* __restrict__ Wt,
    const float* __restrict__ Wx, const float* __restrict__ bh)
{
    __shared__ __align__(16) float W_s[128*U_];   // 32KB (half of W)
    __shared__ __align__(16) float x_s[16*D_];    // 16KB

    const int bid = blockIdx.x;
    const bool is_k = bid >= (B_*L_/16);
    const int rb = is_k ? bid - (B_*L_/16) : bid;
    const float* __restrict__ W = is_k ? Wx : Wt;
    const int t = threadIdx.x;
    const int row0 = rb * 16;

    for (int i = t; i < 16*D_; i += 128)
        x_s[i] = X[row0*D_ + i];

    const int quad = t & 15;        // u = quad*4 .. +3
    const int r    = t >> 4;        // rows r and r+8
    const float* xr0 = x_s + r*D_;
    const float* xr1 = x_s + (r+8)*D_;

    unsigned long long a01_0 = 0ull, a23_0 = 0ull;
    unsigned long long a01_1 = 0ull, a23_1 = 0ull;

    #pragma unroll
    for (int half = 0; half < 2; ++half) {
        __syncthreads();
        for (int i = t; i < 128*U_; i += 128) W_s[i] = W[half*128*U_ + i];
        __syncthreads();
        const float* x0 = xr0 + half*128;
        const float* x1 = xr1 + half*128;
        #pragma unroll 4
        for (int d = 0; d < 128; ++d) {
            ulonglong2 w2 = *reinterpret_cast<const ulonglong2*>(W_s + d*U_ + quad*4);
            unsigned long long xx0 = dup2(x0[d]);
            unsigned long long xx1 = dup2(x1[d]);
            fma2(a01_0, xx0, w2.x);
            fma2(a23_0, xx0, w2.y);
            fma2(a01_1, xx1, w2.x);
            fma2(a23_1, xx1, w2.y);
        }
    }

    float2 v01a = unpack2(a01_0), v23a = unpack2(a23_0);
    float2 v01b = unpack2(a01_1), v23b = unpack2(a23_1);

    if (!is_k) {
        float4 oA; oA.x = v01a.x; oA.y = v01a.y; oA.z = v23a.x; oA.w = v23a.y;
        float4 oB; oB.x = v01b.x; oB.y = v01b.y; oB.z = v23b.x; oB.w = v23b.y;
        *reinterpret_cast<float4*>(g_q + (row0 + r    )*U_ + quad*4) = oA;
        *reinterpret_cast<float4*>(g_q + (row0 + r + 8)*U_ + quad*4) = oB;
    } else {
        float b0 = bh[quad*4+0], b1 = bh[quad*4+1], b2 = bh[quad*4+2], b3 = bh[quad*4+3];
        const int bb  = row0 / L_;
        const int lr  = (row0 % L_);
        float* base = g_kT + bb*U_*L_;
        float vA[4] = { v01a.x+b0, v01a.y+b1, v23a.x+b2, v23a.y+b3 };
        float vB[4] = { v01b.x+b0, v01b.y+b1, v23b.x+b2, v23b.y+b3 };
        #pragma unroll
        for (int c = 0; c < 4; ++c) {
            base[(quad*4+c)*L_ + lr + r    ] = vA[c];
            base[(quad*4+c)*L_ + lr + r + 8] = vB[c];
        }
    }
}

// ---------------------------------------------------------------------------
// Phase 2: causal additive attention. 128 CTAs x 512 threads (16 warps).
// CTA <-> pair {pr, 63-pr} of 8-row tiles (uniform: 9 j-segments of 64 total).
// Score: warp = one row, lane = j-pair; k read DIRECTLY from g_kT via
//        coalesced LDG.64 -> NO smem staging, NO syncs, each warp free-runs.
// Softmax: per-warp (shuffle only), p overwrites scores in smem es[16][512].
// PV: thread t -> (d-quad t&63, 2 rows t>>6); X via LDG.128, p broadcast LDS.
// ---------------------------------------------------------------------------
__global__ void __launch_bounds__(512, 1) attn_kernel(
    const float* __restrict__ X, const float* __restrict__ Wa,
    float* __restrict__ out)
{
    __shared__ __align__(16) float  es[16][L_];   // 32KB  scores -> p
    __shared__ __align__(16) float4 qs4[16*16];   // [row][uq] 4KB
    __shared__ __align__(16) float4 was4[16];     // 256B (Wa * log2e)
    __shared__ float sinv[16];

    const int t = threadIdx.x;
    const int w = t >> 5, lane = t & 31;
    const int b  = blockIdx.x >> 5;
    const int pr = blockIdx.x & 31;
    const int i0A = pr*8, i0B = (63-pr)*8;

    const float* __restrict__ kTb = g_kT + b*U_*L_;
    const float* __restrict__ qb  = g_q  + b*L_*U_;
    const float* __restrict__ Xb  = X    + b*L_*D_;

    if (t < U_) reinterpret_cast<float*>(was4)[t] = Wa[t] * 1.4426950408889634f;
    for (int idx = t; idx < 16*U_; idx += 512) {
        int row = idx >> 6, u = idx & 63;
        int gr = (row < 8) ? (i0A + row) : (i0B + row - 8);
        reinterpret_cast<float*>(qs4)[row*U_ + u] = qb[gr*U_ + u];
    }
    __syncthreads();

    // ================= Phase A: scores (sync-free, per-warp) =================
    const int gi   = (w < 8) ? (i0A + w) : (i0B + w - 8);
    const int nseg = (gi >> 6) + 1;            // 64-j segments (uniform per tile)
    const float4* qsr = qs4 + w*16;
    const int jj0 = 2*lane;

    float m_lane = -1e30f;
    for (int seg = 0; seg < nseg; ++seg) {
        const int jj = seg*64 + jj0;
        const float* kp = kTb + jj;
        unsigned long long e2a = 0ull, e2b = 0ull;
        #pragma unroll
        for (int uq = 0; uq < 16; ++uq) {
            float4 qv = qsr[uq];                 // broadcast LDS
            float4 wv = was4[uq];                // broadcast LDS
            float2 k0 = *reinterpret_cast<const float2*>(kp + (uq*4+0)*L_);
            float2 k1 = *reinterpret_cast<const float2*>(kp + (uq*4+1)*L_);
            float2 k2 = *reinterpret_cast<const float2*>(kp + (uq*4+2)*L_);
            float2 k3 = *reinterpret_cast<const float2*>(kp + (uq*4+3)*L_);
            float t0, t1;
            t0 = tanh_ap(qv.x + k0.x); t1 = tanh_ap(qv.x + k0.y);
            fma2(e2a, dup2(wv.x), pack2f(t0, t1));
            t0 = tanh_ap(qv.y + k1.x); t1 = tanh_ap(qv.y + k1.y);
            fma2(e2b, dup2(wv.y), pack2f(t0, t1));
            t0 = tanh_ap(qv.z + k2.x); t1 = tanh_ap(qv.z + k2.y);
            fma2(e2a, dup2(wv.z), pack2f(t0, t1));
            t0 = tanh_ap(qv.w + k3.x); t1 = tanh_ap(qv.w + k3.y);
            fma2(e2b, dup2(wv.w), pack2f(t0, t1));
        }
        float2 ea = unpack2(e2a), eb = unpack2(e2b);
        float elo = ea.x + eb.x;
        float ehi = ea.y + eb.y;
        if (jj     > gi) elo = -1e30f;    // causal: exp2 -> exact 0 (== ref -10000 path)
        if (jj + 1 > gi) ehi = -1e30f;
        *reinterpret_cast<float2*>(&es[w][jj]) = make_float2(elo, ehi);
        m_lane = fmaxf(m_lane, fmaxf(elo, ehi));
    }

    // ================= Phase B: per-warp softmax =================
    #pragma unroll
    for (int off = 16; off; off >>= 1)
        m_lane = fmaxf(m_lane, __shfl_xor_sync(0xffffffffu, m_lane, off));
    const float m = m_lane;
    float s_lane = 0.f;
    float2* esw = reinterpret_cast<float2*>(&es[w][0]);
    const int n2 = nseg * 32;
    for (int idx = lane; idx < n2; idx += 32) {
        float2 v = esw[idx];
        float p0 = ex2_ap(v.x - m);
        float p1 = ex2_ap(v.y - m);
        esw[idx] = make_float2(p0, p1);
        s_lane += p0 + p1;
    }
    #pragma unroll
    for (int off = 16; off; off >>= 1)
        s_lane += __shfl_xor_sync(0xffffffffu, s_lane, off);
    if (lane == 0) sinv[w] = 1.0f / s_lane;
    __syncthreads();   // p + sinv visible to all

    // ================= Phase C: PV GEMM =================
    const int dq = t & 63;              // d-quad: d = dq*4 .. +3
    const int g  = t >> 6;              // 0..7 -> local rows g*2, g*2+1
    const int lr0 = g*2, lr1 = g*2 + 1;
    const int iT   = (g < 4) ? i0A : i0B;
    const int grow0 = iT + ((g < 4) ? lr0 : (lr0 - 8));
    const int jend  = ((iT >> 6) + 1) * 64;
    const float4* __restrict__ X4 = reinterpret_cast<const float4*>(Xb);
    const float4* p0r = reinterpret_cast<const float4*>(&es[lr0][0]);
    const float4* p1r = reinterpret_cast<const float4*>(&es[lr1][0]);

    unsigned long long a0x = 0ull, a0y = 0ull, a1x = 0ull, a1y = 0ull;
    for (int jb = 0; jb < jend; jb += 8) {
        float4 xv[8];
        #pragma unroll
        for (int j = 0; j < 8; ++j)
            xv[j] = X4[(jb + j)*(D_/4) + dq];            // coalesced LDG.128
        float4 pq0a = p0r[(jb >> 2)], pq0b = p0r[(jb >> 2) + 1];   // broadcast
        float4 pq1a = p1r[(jb >> 2)], pq1b = p1r[(jb >> 2) + 1];
        const float* pp0a = reinterpret_cast<const float*>(&pq0a);
        const float* pp0b = reinterpret_cast<const float*>(&pq0b);
        const float* pp1a = reinterpret_cast<const float*>(&pq1a);
        const float* pp1b = reinterpret_cast<const float*>(&pq1b);
        #pragma unroll
        for (int j = 0; j < 4; ++j) {
            unsigned long long xlo = pack2f(xv[j].x, xv[j].y);
            unsigned long long xhi = pack2f(xv[j].z, xv[j].w);
            unsigned long long pd0 = dup2(pp0a[j]);
            unsigned long long pd1 = dup2(pp1a[j]);
            fma2(a0x, xlo, pd0); fma2(a0y, xhi, pd0);
            fma2(a1x, xlo, pd1); fma2(a1y, xhi, pd1);
        }
        #pragma unroll
        for (int j = 0; j < 4; ++j) {
            unsigned long long xlo = pack2f(xv[4+j].x, xv[4+j].y);
            unsigned long long xhi = pack2f(xv[4+j].z, xv[4+j].w);
            unsigned long long pd0 = dup2(pp0b[j]);
            unsigned long long pd1 = dup2(pp1b[j]);
            fma2(a0x, xlo, pd0); fma2(a0y, xhi, pd0);
            fma2(a1x, xlo, pd1); fma2(a1y, xhi, pd1);
        }
    }

    // ---- finalize ----
    {
        const float is0 = sinv[lr0];
        const float is1 = sinv[lr1];
        float2 vx = unpack2(a0x), vy = unpack2(a0y);
        float4 o0; o0.x = vx.x*is0; o0.y = vx.y*is0; o0.z = vy.x*is0; o0.w = vy.y*is0;
        *reinterpret_cast<float4*>(out + (b*L_ + grow0    )*D_ + dq*4) = o0;
        vx = unpack2(a1x); vy = unpack2(a1y);
        float4 o1; o1.x = vx.x*is1; o1.y = vx.y*is1; o1.z = vy.x*is1; o1.w = vy.y*is1;
        *reinterpret_cast<float4*>(out + (b*L_ + grow0 + 1)*D_ + dq*4) = o1;
    }
}

// ---------------------------------------------------------------------------
extern "C" void kernel_launch(void* const* d_in, const int* in_sizes, int n_in,
                              void* d_out, int out_size)
{
    const float* X  = (const float*)d_in[0];
    const float* Wt = (const float*)d_in[1];
    const float* Wx = (const float*)d_in[2];
    const float* bh = (const float*)d_in[3];
    const float* Wa = (const float*)d_in[4];
    // d_in[5] = ba : constant shift inside softmax -> mathematically a no-op

    proj_kernel<<<2*(B_*L_/16), 128>>>(X, Wt, Wx, bh);
    attn_kernel<<<B_*32, 512>>>(X, Wa, (float*)d_out);
}

// round 7
// speedup vs baseline: 3.2314x; 3.2314x over previous
#include <cuda_runtime.h>
#include <cstdint>

#define B_ 4
#define L_ 512
#define D_ 256
#define U_ 64
#define TI 8
#define TJ 32
#define NTROW (L_/TI)   // 64 row tiles per batch

// scratch for projections (allowed: __device__ globals, no allocation)
__device__ float g_q[B_*L_*U_];
__device__ float g_k[B_*L_*U_];

__device__ __forceinline__ float tanh_ap(float x){ float y; asm("tanh.approx.f32 %0, %1;" : "=f"(y) : "f"(x)); return y; }
__device__ __forceinline__ float ex2_ap(float x){ float y; asm("ex2.approx.f32 %0, %1;" : "=f"(y) : "f"(x)); return y; }
__device__ __forceinline__ unsigned long long dup2(float x){
    unsigned long long r; asm("mov.b64 %0, {%1, %1};" : "=l"(r) : "f"(x)); return r;
}
__device__ __forceinline__ void fma2(unsigned long long &a, unsigned long long x, unsigned long long y){
    asm("fma.rn.f32x2 %0, %1, %2, %0;" : "+l"(a) : "l"(x), "l"(y));
}
__device__ __forceinline__ void mul2(unsigned long long &a, unsigned long long x){
    asm("mul.rn.f32x2 %0, %0, %1;" : "+l"(a) : "l"(x));
}
__device__ __forceinline__ float2 unpack2(unsigned long long v){
    float lo, hi; asm("mov.b64 {%0, %1}, %2;" : "=f"(lo), "=f"(hi) : "l"(v)); return make_float2(lo, hi);
}
__device__ __forceinline__ unsigned smem_u32(const void* p){
    return (unsigned)__cvta_generic_to_shared(p);
}
__device__ __forceinline__ void cp16(unsigned dst, const void* src){
    asm volatile("cp.async.cg.shared.global [%0], [%1], 16;" :: "r"(dst), "l"(src));
}
__device__ __forceinline__ void cp_commit(){ asm volatile("cp.async.commit_group;"); }
__device__ __forceinline__ void cp_wait0(){ asm volatile("cp.async.wait_group 0;"); }

// ---------------------------------------------------------------------------
// Phase 1: q = X@Wt ; k = X@Wx + bh   (packed f32x2 over u-pairs)
// 256 blocks x 128 threads. Each block: 16 rows (2 rows/thread).
// ---------------------------------------------------------------------------
__global__ void __launch_bounds__(128) proj_kernel(
    const float* __restrict__ X, const float* __restrict__ Wt,
    const float* __restrict__ Wx, const float* __restrict__ bh)
{
    __shared__ __align__(16) float W_s[128*U_];   // 32KB (half of W)
    __shared__ __align__(16) float x_s[16*D_];    // 16KB

    const int bid = blockIdx.x;
    const bool is_k = bid >= (B_*L_/16);
    const int rb = is_k ? bid - (B_*L_/16) : bid;
    const float* __restrict__ W = is_k ? Wx : Wt;
    const int t = threadIdx.x;
    const int row0 = rb * 16;

    for (int i = t; i < 16*D_; i += 128)
        x_s[i] = X[row0*D_ + i];

    const int quad = t & 15;
    const int r    = t >> 4;
    const float* xr0 = x_s + r*D_;
    const float* xr1 = x_s + (r+8)*D_;

    unsigned long long a01_0 = 0ull, a23_0 = 0ull;
    unsigned long long a01_1 = 0ull, a23_1 = 0ull;

    #pragma unroll
    for (int half = 0; half < 2; ++half) {
        __syncthreads();
        for (int i = t; i < 128*U_; i += 128) W_s[i] = W[half*128*U_ + i];
        __syncthreads();
        const float* x0 = xr0 + half*128;
        const float* x1 = xr1 + half*128;
        #pragma unroll 4
        for (int d = 0; d < 128; ++d) {
            ulonglong2 w2 = *reinterpret_cast<const ulonglong2*>(W_s + d*U_ + quad*4);
            unsigned long long xx0 = dup2(x0[d]);
            unsigned long long xx1 = dup2(x1[d]);
            fma2(a01_0, xx0, w2.x);
            fma2(a23_0, xx0, w2.y);
            fma2(a01_1, xx1, w2.x);
            fma2(a23_1, xx1, w2.y);
        }
    }

    float bx = 0.f, by = 0.f, bz = 0.f, bw = 0.f;
    if (is_k) { bx = bh[quad*4+0]; by = bh[quad*4+1]; bz = bh[quad*4+2]; bw = bh[quad*4+3]; }

    float* base = (is_k ? g_k : g_q);
    {
        float2 v01 = unpack2(a01_0), v23 = unpack2(a23_0);
        float4 o; o.x = v01.x+bx; o.y = v01.y+by; o.z = v23.x+bz; o.w = v23.y+bw;
        *reinterpret_cast<float4*>(base + (row0 + r)*U_ + quad*4) = o;
    }
    {
        float2 v01 = unpack2(a01_1), v23 = unpack2(a23_1);
        float4 o; o.x = v01.x+bx; o.y = v01.y+by; o.z = v23.x+bz; o.w = v23.y+bw;
        *reinterpret_cast<float4*>(base + (row0 + r + 8)*U_ + quad*4) = o;
    }
}

// ---------------------------------------------------------------------------
// Phase 2: R1 structure (best measured) + cp.async double-buffered fills +
// vectorized p reads. 128 CTAs x 256 threads, pairs {pr, 63-pr}.
// Dynamic smem layout:
//   kbuf : 2 x 512 float4   (16KB)   [buf][uq*TJ + j]
//   Xs   : 2 x 8192 float   (64KB)   [buf][j*D_ + d]
//   q_q  : 128 float4       (2KB)    [uq*TI + i]
//   wa4  : 16 float4        (256B)
//   p4   : 8 x 32 float     (1KB)
//   alpha_s, sinv : 8 + 8 floats
// ---------------------------------------------------------------------------
__global__ void __launch_bounds__(256, 1) attn_kernel(
    const float* __restrict__ X, const float* __restrict__ Wa,
    float* __restrict__ out)
{
    extern __shared__ __align__(16) unsigned char smem_raw[];
    float4* kbuf   = reinterpret_cast<float4*>(smem_raw);                       // 16KB
    float*  Xs     = reinterpret_cast<float*>(smem_raw + 16384);                // 64KB
    float4* q_q    = reinterpret_cast<float4*>(smem_raw + 16384 + 65536);       // 2KB
    float4* wa4    = q_q + 128;                                                 // 256B
    float*  p4     = reinterpret_cast<float*>(wa4 + 16);                        // 1KB
    float*  alpha_s = p4 + TI*TJ;
    float*  sinv    = alpha_s + TI;

    const int t = threadIdx.x;
    const int w = t >> 5, lane = t & 31;
    const int b  = blockIdx.x >> 5;
    const int pr = blockIdx.x & 31;

    const float* __restrict__ Xb = X   + b*L_*D_;
    const float* __restrict__ kb = g_k + b*L_*U_;
    const float* __restrict__ qb = g_q + b*L_*U_;

    if (t < U_) reinterpret_cast<float*>(wa4)[t] = Wa[t] * 1.4426950408889634f;

    // cp.async fill targets for this thread (tile-invariant parts)
    const int kf_uq0 = t & 15,        kf_j0 = t >> 4;           // k rep 0
    const int kf_uq1 = (t+256) & 15,  kf_j1 = (t+256) >> 4;     // k rep 1
    const unsigned k_dst0 = smem_u32(kbuf) + (kf_uq0*TJ + kf_j0)*16;
    const unsigned k_dst1 = smem_u32(kbuf) + (kf_uq1*TJ + kf_j1)*16;
    const unsigned x_dst0 = smem_u32(Xs) + t*16;                // rep r: + r*4096B
    const unsigned KBUF_B = 512*16;                              // 8KB per buffer
    const unsigned XS_B   = 8192*4;                              // 32KB per buffer

    const int dp  = t & 127;   // d pair index (d = 2dp, 2dp+1)
    const int ih  = t >> 7;
    const int ib0 = ih * 4;    // PV rows ib0..ib0+3

    for (int pass = 0; pass < 2; ++pass) {
        const int it = pass ? (NTROW - 1 - pr) : pr;
        const int i0 = it * TI;
        const int ntj = (i0 + TI - 1)/TJ + 1;
        const int gi = i0 + w;

        __syncthreads();   // prior pass fully done with smem
        if (t < 16*TI) {
            int i = t >> 4, uq = t & 15;
            q_q[uq*TI + i] = *reinterpret_cast<const float4*>(qb + (i0+i)*U_ + uq*4);
        }
        // prologue: async-fill buffer 0 (k + X for j-tile 0)
        {
            cp16(k_dst0, kb + kf_j0*U_ + kf_uq0*4);
            cp16(k_dst1, kb + kf_j1*U_ + kf_uq1*4);
            #pragma unroll
            for (int rep = 0; rep < 8; ++rep) {
                int idx = t + rep*256;           // row=idx>>6, c4=idx&63
                cp16(x_dst0 + rep*4096, Xb + (idx>>6)*D_ + (idx&63)*4);
            }
            cp_commit();
        }

        float m_run = -1e30f, s_run = 0.f;
        unsigned long long acc[4] = {0ull, 0ull, 0ull, 0ull};

        for (int jt = 0; jt < ntj; ++jt) {
            const int j0 = jt * TJ;
            const int cur = jt & 1;

            cp_wait0();        // this thread's fill for tile jt landed
            __syncthreads();   // all threads' fills visible; prev PV done with other buf

            // issue async fill for tile jt+1 into the other buffer
            if (jt + 1 < ntj) {
                const int nxt = (jt + 1) & 1;
                const int j0n = j0 + TJ;
                cp16(k_dst0 + nxt*KBUF_B, kb + (j0n + kf_j0)*U_ + kf_uq0*4);
                cp16(k_dst1 + nxt*KBUF_B, kb + (j0n + kf_j1)*U_ + kf_uq1*4);
                #pragma unroll
                for (int rep = 0; rep < 8; ++rep) {
                    int idx = t + rep*256;
                    cp16(x_dst0 + nxt*XS_B + rep*4096, Xb + (j0n + (idx>>6))*D_ + (idx&63)*4);
                }
                cp_commit();
            }

            // ---- score: e[gi][j0+lane] in log2 domain ----
            const float4* kc = kbuf + cur*512;
            float e0 = 0.f, e1 = 0.f;
            #pragma unroll
            for (int uq = 0; uq < 16; ++uq) {
                float4 kv = kc[uq*TJ + lane];    // conflict-free
                float4 qv = q_q[uq*TI + w];      // broadcast
                float4 wa = wa4[uq];             // broadcast
                e0 += wa.x * tanh_ap(qv.x + kv.x);
                e1 += wa.y * tanh_ap(qv.y + kv.y);
                e0 += wa.z * tanh_ap(qv.z + kv.z);
                e1 += wa.w * tanh_ap(qv.w + kv.w);
            }
            float e = e0 + e1;
            const int gj = j0 + lane;
            if (gj > gi) e = -1e30f;   // causal: exp2 underflows to exact 0

            // ---- online softmax (warp = one row) ----
            float mt = e;
            #pragma unroll
            for (int off = 16; off; off >>= 1)
                mt = fmaxf(mt, __shfl_xor_sync(0xffffffffu, mt, off));
            float m_new = fmaxf(m_run, mt);
            float p = ex2_ap(e - m_new);
            float st = p;
            #pragma unroll
            for (int off = 16; off; off >>= 1)
                st += __shfl_xor_sync(0xffffffffu, st, off);
            float alpha = ex2_ap(m_run - m_new);
            s_run = s_run * alpha + st;
            m_run = m_new;
            p4[w*TJ + lane] = p;
            if (lane == 0) alpha_s[w] = alpha;
            __syncthreads();

            // ---- PV update (packed f32x2 over d-pairs; p via LDS.128 + ALU dup) ----
            #pragma unroll
            for (int i = 0; i < 4; ++i)
                mul2(acc[i], dup2(alpha_s[ib0+i]));

            const unsigned long long* xcol =
                reinterpret_cast<const unsigned long long*>(Xs + cur*8192) + dp; // row stride 128
            #pragma unroll
            for (int jc = 0; jc < TJ/4; ++jc) {
                unsigned long long xv0 = xcol[(jc*4+0)*(D_/2)];
                unsigned long long xv1 = xcol[(jc*4+1)*(D_/2)];
                unsigned long long xv2 = xcol[(jc*4+2)*(D_/2)];
                unsigned long long xv3 = xcol[(jc*4+3)*(D_/2)];
                float4 pv[4];
                #pragma unroll
                for (int i = 0; i < 4; ++i)
                    pv[i] = *reinterpret_cast<const float4*>(&p4[(ib0+i)*TJ + jc*4]); // broadcast
                #pragma unroll
                for (int i = 0; i < 4; ++i) {
                    const float* pf = reinterpret_cast<const float*>(&pv[i]);
                    fma2(acc[i], xv0, dup2(pf[0]));
                    fma2(acc[i], xv1, dup2(pf[1]));
                    fma2(acc[i], xv2, dup2(pf[2]));
                    fma2(acc[i], xv3, dup2(pf[3]));
                }
            }
            __syncthreads();   // p4/alpha consumed before next overwrite
        }

        // ---- finalize ----
        if (lane == 0) sinv[w] = 1.0f / s_run;
        __syncthreads();
        #pragma unroll
        for (int i = 0; i < 4; ++i) {
            float2 v = unpack2(acc[i]);
            float is = sinv[ib0 + i];
            float2 o = make_float2(v.x * is, v.y * is);
            *reinterpret_cast<float2*>(out + (b*L_ + i0 + ib0 + i)*D_ + dp*2) = o;
        }
    }
}

// ---------------------------------------------------------------------------
extern "C" void kernel_launch(void* const* d_in, const int* in_sizes, int n_in,
                              void* d_out, int out_size)
{
    const float* X  = (const float*)d_in[0];
    const float* Wt = (const float*)d_in[1];
    const float* Wx = (const float*)d_in[2];
    const float* bh = (const float*)d_in[3];
    const float* Wa = (const float*)d_in[4];
    // d_in[5] = ba : constant shift inside softmax -> mathematically a no-op

    const int attn_smem = 16384 + 65536 + 2048 + 256 + 1024 + 128;  // ~85.3KB
    cudaFuncSetAttribute(attn_kernel, cudaFuncAttributeMaxDynamicSharedMemorySize, attn_smem);

    proj_kernel<<<2*(B_*L_/16), 128>>>(X, Wt, Wx, bh);
    attn_kernel<<<B_*(NTROW/2), 256, attn_smem>>>(X, Wa, (float*)d_out);
}